// round 17
// baseline (speedup 1.0000x reference)
#include <cuda_runtime.h>

// h_t = alpha_t * h_{t-1} + x_t over axis 1 of float32 [4, 8192, 1024].
// Persistent scan, cp.async smem pipeline (R16 WIN) with LSU-slimmed consumer:
//  - 3 stages x 256-row chunks (2 in flight), cp.async.cg 16B units
//  - thread owns a d-pair: LDS.64 data reads, STG.64 stores
//  - warp = 16 d-pairs x 2 row-halves (8 rows each), halves merged by shuffle
//  - per-warp aggregates packed float4 {Px,Py,Lx,Ly}: fold = 16 LDS.128
//  - lagged finalize (fold+store of chunk k-1 during chunk k) -> one
//    __syncthreads per chunk orders data, aggregates, and stage reuse.

#define B_      4
#define S_      8192
#define D_      1024
#define TPB_    512
#define NW_     16
#define ROWS_   256                   // rows per chunk
#define RT_     8                     // rows per thread (one row-half)
#define ITERS_  (S_ / ROWS_)          // 32 chunks per chain
#define NSTG_   3                     // smem pipeline stages
#define LG_     (B_ * (D_ / 32))      // 128 chains = 128 blocks

#define STAGE_F (NSTG_ * 2 * ROWS_ * 32)          // 49152 floats
#define AGG_F   (2 * NW_ * 16 * 4)                // 2 bufs x 16 warps x 16 dp x float4
#define SMEM_B  ((STAGE_F + AGG_F) * 4)           // 204800 bytes

static __device__ __forceinline__ void cp16(float* dst, const float* src) {
    unsigned int da = (unsigned int)__cvta_generic_to_shared(dst);
    asm volatile("cp.async.cg.shared.global [%0], [%1], 16;" :: "r"(da), "l"(src) : "memory");
}
static __device__ __forceinline__ float2 fma2(float2 a, float2 b, float2 c) {
    return make_float2(fmaf(a.x, b.x, c.x), fmaf(a.y, b.y, c.y));
}
static __device__ __forceinline__ float2 mul2(float2 a, float2 b) {
    return make_float2(a.x * b.x, a.y * b.y);
}

__global__ __launch_bounds__(TPB_, 1) void scan_kernel(const float* __restrict__ x,
                                                       const float* __restrict__ alpha,
                                                       float* __restrict__ out) {
    extern __shared__ float sm[];
    float*  stage = sm;                                  // [stg][tensor][row][32f]
    float4* agg   = (float4*)(sm + STAGE_F);             // [buf][warp][dp]

    const int tid  = threadIdx.x;
    const int lane = tid & 31;
    const int w    = tid >> 5;
    const int dp   = lane & 15;          // d-pair index within 32-d tile
    const int rh   = lane >> 4;          // row-half (0: rows 0-7, 1: rows 8-15 of warp slab)
    const int lg   = blockIdx.x;         // chain: b * 32 + dtile
    const int b    = lg >> 5;
    const int dt   = lg & 31;
    const int d0   = dt * 32;
    const int d    = d0 + dp * 2;

    // ---- copy producer for chunk c: 2048 16B-units per tensor, 4/thread ----
    #define ISSUE(c)                                                          \
    {                                                                         \
        const size_t eb = ((size_t)b * S_ + (size_t)(c) * ROWS_) * D_ + d0;   \
        float* stA = stage + (((c) % NSTG_) * 2 + 0) * (ROWS_ * 32);          \
        float* stX = stage + (((c) % NSTG_) * 2 + 1) * (ROWS_ * 32);          \
        _Pragma("unroll")                                                     \
        for (int i = 0; i < 4; i++) {                                         \
            const int u = tid + i * TPB_;   /* row = u>>3, 16B col = u&7 */   \
            const size_t off = eb + (size_t)(u >> 3) * D_ + (size_t)(u & 7) * 4; \
            cp16(stA + u * 4, alpha + off);                                   \
            cp16(stX + u * 4, x + off);                                       \
        }                                                                     \
    }

    // Prologue: chunks 0,1 in flight.
    ISSUE(0); asm volatile("cp.async.commit_group;" ::: "memory");
    ISSUE(1); asm volatile("cp.async.commit_group;" ::: "memory");

    float2 Ap[RT_], Xp[RT_];             // held scan results of chunk k-1
    float2 prevP0, prevL0;               // held low-half (P,L) for rh=1 carry
    float2 cin = make_float2(0.f, 0.f);
    size_t prev_sb = 0;

#pragma unroll 1
    for (int k = 0; k < ITERS_; k++) {
        // group k complete (k+1 may still be in flight)
        asm volatile("cp.async.wait_group 1;" ::: "memory");
        __syncthreads();   // chunk-k data visible to all; agg[k-1] visible; stage slot (k+2)%3 free

        if (k + 2 < ITERS_) ISSUE(k + 2);
        asm volatile("cp.async.commit_group;" ::: "memory");

        // ---- consume chunk k: LDS.64 + local scan over 8 rows x d-pair ----
        const float* stA = stage + ((k % NSTG_) * 2 + 0) * (ROWS_ * 32);
        const float* stX = stage + ((k % NSTG_) * 2 + 1) * (ROWS_ * 32);
        const int rowbase = w * 16 + rh * RT_;
        float2 a[RT_], xv[RT_];
#pragma unroll
        for (int r = 0; r < RT_; r++)
            a[r]  = *(const float2*)&stA[(rowbase + r) * 32 + dp * 2];
#pragma unroll
        for (int r = 0; r < RT_; r++)
            xv[r] = *(const float2*)&stX[(rowbase + r) * 32 + dp * 2];

        float2 P = make_float2(1.f, 1.f), L = make_float2(0.f, 0.f);
#pragma unroll
        for (int r = 0; r < RT_; r++) {
            L = fma2(a[r], L, xv[r]);
            P = mul2(P, a[r]);
            a[r]  = P;    // per-row cumprod
            xv[r] = L;    // per-row local scan
        }

        // merge row-halves: rh=1 needs rh=0's (P,L); warp aggregate = combined.
        const int src = lane & 15;       // low-half lane with same dp
        float2 p0, l0;
        p0.x = __shfl_sync(0xffffffffu, P.x, src);
        p0.y = __shfl_sync(0xffffffffu, P.y, src);
        l0.x = __shfl_sync(0xffffffffu, L.x, src);
        l0.y = __shfl_sync(0xffffffffu, L.y, src);
        if (rh) {   // upper half publishes the 16-row warp aggregate
            float2 pw = mul2(P, p0);
            float2 lw = fma2(P, l0, L);
            agg[(k & 1) * (NW_ * 16) + w * 16 + dp] = make_float4(pw.x, pw.y, lw.x, lw.y);
        }

        // ---- finalize chunk k-1: fold its aggregates, apply carry, store ----
        if (k > 0) {
            const float4* ag = agg + ((k - 1) & 1) * (NW_ * 16);
            float2 acc = cin, h0w = cin;
#pragma unroll
            for (int w2 = 0; w2 < NW_; w2++) {
                if (w2 == w) h0w = acc;
                const float4 v = ag[w2 * 16 + dp];
                acc = make_float2(fmaf(v.x, acc.x, v.z), fmaf(v.y, acc.y, v.w));
            }
            cin = acc;
            const float2 hs = rh ? fma2(prevP0, h0w, prevL0) : h0w;
#pragma unroll
            for (int r = 0; r < RT_; r++) {
                float2 o = fma2(Ap[r], hs, Xp[r]);
                __stcs((float2*)(out + prev_sb + (size_t)r * D_), o);
            }
        }

        // rotate held state
#pragma unroll
        for (int r = 0; r < RT_; r++) { Ap[r] = a[r]; Xp[r] = xv[r]; }
        prevP0 = p0; prevL0 = l0;
        prev_sb = ((size_t)b * S_ + (size_t)k * ROWS_ + rowbase) * D_ + d;
    }

    // ---- epilogue: finalize last chunk ----
    __syncthreads();
    {
        const float4* ag = agg + ((ITERS_ - 1) & 1) * (NW_ * 16);
        float2 acc = cin, h0w = cin;
#pragma unroll
        for (int w2 = 0; w2 < NW_; w2++) {
            if (w2 == w) h0w = acc;
            const float4 v = ag[w2 * 16 + dp];
            acc = make_float2(fmaf(v.x, acc.x, v.z), fmaf(v.y, acc.y, v.w));
        }
        const float2 hs = rh ? fma2(prevP0, h0w, prevL0) : h0w;
#pragma unroll
        for (int r = 0; r < RT_; r++) {
            float2 o = fma2(Ap[r], hs, Xp[r]);
            __stcs((float2*)(out + prev_sb + (size_t)r * D_), o);
        }
    }
    #undef ISSUE
}

extern "C" void kernel_launch(void* const* d_in, const int* in_sizes, int n_in,
                              void* d_out, int out_size) {
    const float* xp = (const float*)d_in[0];
    const float* ap = (const float*)d_in[1];
    float* op = (float*)d_out;

    static int configured = 0;
    if (!configured) {
        cudaFuncSetAttribute(scan_kernel, cudaFuncAttributeMaxDynamicSharedMemorySize, SMEM_B);
        configured = 1;
    }
    scan_kernel<<<LG_, TPB_, SMEM_B>>>(xp, ap, op);
}